// round 2
// baseline (speedup 1.0000x reference)
#include <cuda_runtime.h>

#define B_   8
#define LQ   5376
#define NQ   (B_*LQ)   // 43008

// Scratch buffers (no cudaMalloc allowed)
__device__ float g_value[(size_t)NQ * 128];   // (B,Lq,16,8)
__device__ float g_offs [(size_t)NQ * 384];   // (B,Lq,16,3,4,2)
__device__ float g_attn [(size_t)NQ * 192];   // (B,Lq,16,12) raw logits
__device__ float g_sampled[(size_t)NQ * 128]; // (B,Lq,16,8) after sampling

// ---------------------------------------------------------------------------
// Kernel 1: fused projection GEMM  x[NQ,128] @ [W_val | W_off | W_attn] + bias
// x is gathered on the fly from the 3 feature maps (x[b,q,k] = fm_l[b,k,pos]).
// Tile 64 queries x 64 cols, K chunked by 64, 4x4 per-thread micro-tile.
// ---------------------------------------------------------------------------
__global__ __launch_bounds__(256) void proj_kernel(
    const float* __restrict__ fm0, const float* __restrict__ fm1, const float* __restrict__ fm2,
    const float* __restrict__ Wv, const float* __restrict__ bv,
    const float* __restrict__ Wo, const float* __restrict__ bo,
    const float* __restrict__ Wa, const float* __restrict__ ba)
{
    __shared__ float As[64][64];   // [k][r]
    __shared__ float Ws[64][64];   // [k][c]

    const int tid = threadIdx.x;
    const int qg0 = blockIdx.x * 64;
    const int n0  = blockIdx.y * 64;

    // Per-thread gather base for x loads: r = query within tile
    const int r  = tid & 63;
    const int kb = tid >> 6;   // 0..3
    {
        // nothing
    }
    const int qg = qg0 + r;
    const int b  = qg / LQ;
    const int q  = qg - b * LQ;
    const float* fmp; int HW, pos;
    if (q < 4096)      { fmp = fm0; HW = 4096; pos = q; }
    else if (q < 5120) { fmp = fm1; HW = 1024; pos = q - 4096; }
    else               { fmp = fm2; HW = 256;  pos = q - 5120; }
    const float* xbase = fmp + (size_t)b * 128 * HW + pos;

    // This block's 64 columns lie entirely inside one of the three matrices
    const float* Wm; const float* bm; int wstride; int nloc0;
    if (n0 < 128)      { Wm = Wv; bm = bv; wstride = 128; nloc0 = n0; }
    else if (n0 < 512) { Wm = Wo; bm = bo; wstride = 384; nloc0 = n0 - 128; }
    else               { Wm = Wa; bm = ba; wstride = 192; nloc0 = n0 - 512; }

    const int c  = tid & 63;
    const int tx = tid & 15, ty = tid >> 4;
    const int r0 = ty * 4, c0 = tx * 4;

    float acc[4][4];
    #pragma unroll
    for (int i = 0; i < 4; i++)
        #pragma unroll
        for (int j = 0; j < 4; j++) acc[i][j] = 0.f;

    for (int kk = 0; kk < 128; kk += 64) {
        #pragma unroll
        for (int i = 0; i < 16; i++) {
            int k = kb + i * 4;                        // 0..63
            As[k][r] = xbase[(size_t)(kk + k) * HW];   // coalesced over r
        }
        #pragma unroll
        for (int i = 0; i < 16; i++) {
            int k = kb + i * 4;
            Ws[k][c] = Wm[(size_t)(kk + k) * wstride + nloc0 + c];  // coalesced over c
        }
        __syncthreads();
        #pragma unroll
        for (int k = 0; k < 64; k++) {
            float4 a = *(const float4*)&As[k][r0];
            float4 w = *(const float4*)&Ws[k][c0];
            acc[0][0] += a.x * w.x; acc[0][1] += a.x * w.y; acc[0][2] += a.x * w.z; acc[0][3] += a.x * w.w;
            acc[1][0] += a.y * w.x; acc[1][1] += a.y * w.y; acc[1][2] += a.y * w.z; acc[1][3] += a.y * w.w;
            acc[2][0] += a.z * w.x; acc[2][1] += a.z * w.y; acc[2][2] += a.z * w.z; acc[2][3] += a.z * w.w;
            acc[3][0] += a.w * w.x; acc[3][1] += a.w * w.y; acc[3][2] += a.w * w.z; acc[3][3] += a.w * w.w;
        }
        __syncthreads();
    }

    // Epilogue: add bias and scatter to the right scratch buffer
    #pragma unroll
    for (int i = 0; i < 4; i++) {
        size_t qg_w = (size_t)(qg0 + r0 + i);
        #pragma unroll
        for (int j = 0; j < 4; j++) {
            int n = n0 + c0 + j;
            float v = acc[i][j] + bm[nloc0 + c0 + j];
            if (n0 < 128)      g_value[qg_w * 128 + n]         = v;
            else if (n0 < 512) g_offs [qg_w * 384 + (n - 128)] = v;
            else               g_attn [qg_w * 192 + (n - 512)] = v;
        }
    }
}

// ---------------------------------------------------------------------------
// Kernel 2: per-query softmax + bilinear sampling.
// One block per (b,q): 128 threads = 16 heads x 8 channels.
// ---------------------------------------------------------------------------
__global__ __launch_bounds__(128) void sample_kernel()
{
    const int qg = blockIdx.x;
    const int t  = threadIdx.x;
    const int h  = t >> 3;
    const int ch = t & 7;

    const int b = qg / LQ;
    const int q = qg - b * LQ;
    int posq, Wq;
    if (q < 4096)      { posq = q;        Wq = 64; }
    else if (q < 5120) { posq = q - 4096; Wq = 32; }
    else               { posq = q - 5120; Wq = 16; }
    const float invWq = 1.f / (float)Wq;
    const float refx = ((posq % Wq) + 0.5f) * invWq;
    const float refy = ((posq / Wq) + 0.5f) * invWq;

    __shared__ float s_attn[192];
    __shared__ float s_offs[384];
    for (int i = t; i < 192; i += 128) s_attn[i] = g_attn[(size_t)qg * 192 + i];
    for (int i = t; i < 384; i += 128) s_offs[i] = g_offs[(size_t)qg * 384 + i];
    __syncthreads();

    // Softmax over the 12 (level,point) logits of this head
    float av[12];
    float m = -1e30f;
    #pragma unroll
    for (int p = 0; p < 12; p++) { av[p] = s_attn[h * 12 + p]; m = fmaxf(m, av[p]); }
    float s = 0.f;
    #pragma unroll
    for (int p = 0; p < 12; p++) { av[p] = __expf(av[p] - m); s += av[p]; }
    const float inv = 1.f / s;

    const int Ws_[3] = {64, 32, 16};
    const int st [3] = {0, 4096, 5120};

    float acc = 0.f;
    #pragma unroll
    for (int l = 0; l < 3; l++) {
        const int   Wl = Ws_[l];
        const float fW = (float)Wl;
        const float* vbase = g_value + ((size_t)(b * LQ + st[l])) * 128 + h * 8 + ch;
        #pragma unroll
        for (int p = 0; p < 4; p++) {
            float ox = s_offs[h * 24 + (l * 4 + p) * 2 + 0];
            float oy = s_offs[h * 24 + (l * 4 + p) * 2 + 1];
            float x = (refx + ox / fW) * fW - 0.5f;
            float y = (refy + oy / fW) * fW - 0.5f;
            float x0f = floorf(x), y0f = floorf(y);
            int   x0 = (int)x0f,  y0 = (int)y0f;
            float wx1 = x - x0f, wx0 = 1.f - wx1;
            float wy1 = y - y0f, wy0 = 1.f - wy1;
            float aw = av[l * 4 + p] * inv;
            #pragma unroll
            for (int dy = 0; dy < 2; dy++) {
                int yi = y0 + dy;
                if ((unsigned)yi >= (unsigned)Wl) continue;
                float wy = dy ? wy1 : wy0;
                #pragma unroll
                for (int dx = 0; dx < 2; dx++) {
                    int xi = x0 + dx;
                    if ((unsigned)xi >= (unsigned)Wl) continue;
                    float wx = dx ? wx1 : wx0;
                    acc += aw * wy * wx * vbase[(size_t)(yi * Wl + xi) * 128];
                }
            }
        }
    }
    g_sampled[(size_t)qg * 128 + t] = acc;
}

// ---------------------------------------------------------------------------
// Kernel 3: output projection  sampled[NQ,128] @ W_out[128,128] + b_out,
// scattered into (B,128,H,W) per-level layout via smem transpose.
// ---------------------------------------------------------------------------
__global__ __launch_bounds__(256) void out_kernel(
    const float* __restrict__ Wout, const float* __restrict__ bout,
    float* __restrict__ out)
{
    __shared__ float As[64][65];   // [r][k]  (+1 pad)
    __shared__ float Ws[64][64];   // [k][c]
    __shared__ float Os[64][65];   // [r][c]  (+1 pad)

    const int tid = threadIdx.x;
    const int qg0 = blockIdx.x * 64;
    const int n0  = blockIdx.y * 64;
    const int tx = tid & 15, ty = tid >> 4;
    const int r0 = ty * 4, c0 = tx * 4;

    float acc[4][4];
    #pragma unroll
    for (int i = 0; i < 4; i++)
        #pragma unroll
        for (int j = 0; j < 4; j++) acc[i][j] = 0.f;

    const int kl = tid & 63;
    const int rb = tid >> 6;

    for (int kk = 0; kk < 128; kk += 64) {
        #pragma unroll
        for (int i = 0; i < 16; i++) {
            int r_ = rb + 4 * i;
            As[r_][kl] = g_sampled[(size_t)(qg0 + r_) * 128 + kk + kl];
        }
        #pragma unroll
        for (int i = 0; i < 16; i++) {
            int k_ = rb + 4 * i;
            Ws[k_][kl] = Wout[(size_t)(kk + k_) * 128 + n0 + kl];
        }
        __syncthreads();
        #pragma unroll
        for (int k = 0; k < 64; k++) {
            float4 w = *(const float4*)&Ws[k][c0];
            float a0 = As[r0 + 0][k], a1 = As[r0 + 1][k];
            float a2 = As[r0 + 2][k], a3 = As[r0 + 3][k];
            acc[0][0] += a0 * w.x; acc[0][1] += a0 * w.y; acc[0][2] += a0 * w.z; acc[0][3] += a0 * w.w;
            acc[1][0] += a1 * w.x; acc[1][1] += a1 * w.y; acc[1][2] += a1 * w.z; acc[1][3] += a1 * w.w;
            acc[2][0] += a2 * w.x; acc[2][1] += a2 * w.y; acc[2][2] += a2 * w.z; acc[2][3] += a2 * w.w;
            acc[3][0] += a3 * w.x; acc[3][1] += a3 * w.y; acc[3][2] += a3 * w.z; acc[3][3] += a3 * w.w;
        }
        __syncthreads();
    }

    #pragma unroll
    for (int i = 0; i < 4; i++)
        #pragma unroll
        for (int j = 0; j < 4; j++)
            Os[r0 + i][c0 + j] = acc[i][j] + bout[n0 + c0 + j];
    __syncthreads();

    // Coalesced scatter: consecutive threads -> consecutive queries (pos)
    for (int cc = 0; cc < 64; cc += 4) {
        int c = cc + (tid >> 6);
        int r = tid & 63;
        int qg = qg0 + r;
        int b = qg / LQ;
        int q = qg - b * LQ;
        int n = n0 + c;
        size_t addr;
        if (q < 4096)      addr = ((size_t)(b * 128 + n)) * 4096 + q;
        else if (q < 5120) addr = 4194304u + ((size_t)(b * 128 + n)) * 1024 + (q - 4096);
        else               addr = 5242880u + ((size_t)(b * 128 + n)) * 256  + (q - 5120);
        out[addr] = Os[r][c];
    }
}

extern "C" void kernel_launch(void* const* d_in, const int* in_sizes, int n_in,
                              void* d_out, int out_size)
{
    const float* fm0   = (const float*)d_in[0];
    const float* fm1   = (const float*)d_in[1];
    const float* fm2   = (const float*)d_in[2];
    const float* W_off = (const float*)d_in[3];
    const float* b_off = (const float*)d_in[4];
    const float* W_att = (const float*)d_in[5];
    const float* b_att = (const float*)d_in[6];
    const float* W_val = (const float*)d_in[7];
    const float* b_val = (const float*)d_in[8];
    const float* W_out = (const float*)d_in[9];
    const float* b_out = (const float*)d_in[10];
    float* out = (float*)d_out;

    dim3 g1(NQ / 64, 11);
    proj_kernel<<<g1, 256>>>(fm0, fm1, fm2, W_val, b_val, W_off, b_off, W_att, b_att);

    sample_kernel<<<NQ, 128>>>();

    dim3 g3(NQ / 64, 2);
    out_kernel<<<g3, 256>>>(W_out, b_out, out);
}